// round 10
// baseline (speedup 1.0000x reference)
#include <cuda_runtime.h>
#include <cuda_fp16.h>
#include <math.h>
#include <stdint.h>

#define HID  1024
#define FFN  4096
#define NE   8
#define NTOK 4096
#define CAP  9216

#define BM 128
#define BN 128
#define BK 32
#define STAGES 3
#define APAD 40                        // halves per A smem row (80 B, conflict-free LDSM)
#define BPAD 136                       // halves per fp16 B k-row (272 B, conflict-free LDSM)
#define B32PAD 132                     // floats per fp32 B k-row (528 B, conflict-free)
#define ABYTES  (BM * APAD * 2)        // 10240
#define B32BYTES (BK * B32PAD * 4)     // 16896
#define B16BYTES (BK * BPAD * 2)       // 8704
#define A_TOT   (STAGES * ABYTES)      // 30720
#define B32_TOT (STAGES * B32BYTES)    // 50688
#define SMEM_TOTAL (A_TOT + B32_TOT + B16BYTES)   // 90112 -> 2 CTAs/SM

// ---------------- scratch (device globals; zero-initialized at load) ----------------
__device__ int    g_cnt[NE];
__device__ int    g_off[NE + 1];
__device__ int    g_end[NE];
__device__ int    g_cur[NE];
__device__ int    g_rowTok[CAP];
__device__ int    g_tok2[NTOK * 2];
__device__ float  g_w2v[NTOK * 2];
__device__ int    g_pairPos[NTOK * 2];
__device__ __half g_Xh[(size_t)CAP * HID];
__device__ __half g_Hh[(size_t)CAP * FFN];
__device__ __half g_Yh[(size_t)CAP * HID];

// ---------------- helpers ----------------
__device__ __forceinline__ uint32_t smem_u32(const void* p) {
    uint32_t a;
    asm("{ .reg .u64 t; cvta.to.shared.u64 t, %1; cvt.u32.u64 %0, t; }" : "=r"(a) : "l"(p));
    return a;
}
__device__ __forceinline__ void cpa16(uint32_t s, const void* g) {
    asm volatile("cp.async.cg.shared.global [%0], [%1], 16;\n" :: "r"(s), "l"(g));
}
__device__ __forceinline__ void ldsm4(unsigned* r, uint32_t a) {
    asm volatile("ldmatrix.sync.aligned.m8n8.x4.shared.b16 {%0,%1,%2,%3}, [%4];"
                 : "=r"(r[0]), "=r"(r[1]), "=r"(r[2]), "=r"(r[3]) : "r"(a));
}
__device__ __forceinline__ void ldsm4t(unsigned* r, uint32_t a) {
    asm volatile("ldmatrix.sync.aligned.m8n8.x4.trans.shared.b16 {%0,%1,%2,%3}, [%4];"
                 : "=r"(r[0]), "=r"(r[1]), "=r"(r[2]), "=r"(r[3]) : "r"(a));
}
__device__ __forceinline__ void sts64(uint32_t a, uint32_t u0, uint32_t u1) {
    asm volatile("st.shared.v2.b32 [%0], {%1,%2};" :: "r"(a), "r"(u0), "r"(u1) : "memory");
}
__device__ __forceinline__ void lds128(float4& v, uint32_t a) {
    asm volatile("ld.shared.v4.f32 {%0,%1,%2,%3}, [%4];"
                 : "=f"(v.x), "=f"(v.y), "=f"(v.z), "=f"(v.w) : "r"(a));
}
__device__ __forceinline__ uint32_t h2u(__half2 h) {
    return *reinterpret_cast<uint32_t*>(&h);
}

// ---------------- routing ----------------
__global__ void k_router(const float* __restrict__ x, const float* __restrict__ Wr) {
    int warp = threadIdx.x >> 5, lane = threadIdx.x & 31;
    int t = blockIdx.x * 8 + warp;
    const float* xr = x + (size_t)t * HID;
    float acc[NE];
#pragma unroll
    for (int e = 0; e < NE; e++) acc[e] = 0.f;
    for (int i = lane; i < HID; i += 32) {
        float xv = xr[i];
        const float4* w = (const float4*)(Wr + (size_t)i * NE);
        float4 w0 = w[0], w1 = w[1];
        acc[0] += xv * w0.x; acc[1] += xv * w0.y; acc[2] += xv * w0.z; acc[3] += xv * w0.w;
        acc[4] += xv * w1.x; acc[5] += xv * w1.y; acc[6] += xv * w1.z; acc[7] += xv * w1.w;
    }
#pragma unroll
    for (int e = 0; e < NE; e++)
#pragma unroll
        for (int s = 16; s > 0; s >>= 1) acc[e] += __shfl_xor_sync(0xffffffffu, acc[e], s);
    if (lane == 0) {
        int i0 = 0; float m0 = acc[0];
#pragma unroll
        for (int e = 1; e < NE; e++) if (acc[e] > m0) { m0 = acc[e]; i0 = e; }
        int i1 = -1; float m1 = -1e30f;
#pragma unroll
        for (int e = 0; e < NE; e++) if (e != i0 && acc[e] > m1) { m1 = acc[e]; i1 = e; }
        float w0 = 1.f / (1.f + expf(m1 - m0));
        g_tok2[2 * t] = i0; g_tok2[2 * t + 1] = i1;
        g_w2v[2 * t] = w0;  g_w2v[2 * t + 1] = 1.f - w0;
        atomicAdd(&g_cnt[i0], 1);
        atomicAdd(&g_cnt[i1], 1);
    }
}

// reads counters, builds offsets, re-zeroes counters for the next replay.
__global__ void k_offsets() {
    if (threadIdx.x == 0) {
        int o = 0;
#pragma unroll
        for (int e = 0; e < NE; e++) {
            int c = g_cnt[e];
            g_off[e] = o; g_end[e] = o + c; g_cur[e] = o;
            o += (c + 127) & ~127;
            g_cnt[e] = 0;
        }
        g_off[NE] = o;
    }
}

__global__ void k_place() {
    int p = blockIdx.x * blockDim.x + threadIdx.x;
    if (p < NTOK * 2) {
        int e = g_tok2[p];
        int r = atomicAdd(&g_cur[e], 1);
        g_rowTok[r] = p >> 1;
        g_pairPos[p] = r;
    }
}

// gather + fp16-convert x into g_Xh; zero pad rows
__global__ void k_gather(const float* __restrict__ x) {
    int r = blockIdx.x;
    bool valid = false;
#pragma unroll
    for (int e = 0; e < NE; e++) valid |= (r >= g_off[e] && r < g_end[e]);
    __half2* dst = (__half2*)(g_Xh + (size_t)r * HID);
    int i = threadIdx.x;  // 256 threads * 4 floats
    if (valid) {
        const float4* src = (const float4*)(x + (size_t)g_rowTok[r] * HID);
        float4 v = src[i];
        dst[2 * i]     = __floats2half2_rn(v.x, v.y);
        dst[2 * i + 1] = __floats2half2_rn(v.z, v.w);
    } else {
        dst[2 * i]     = __floats2half2_rn(0.f, 0.f);
        dst[2 * i + 1] = __floats2half2_rn(0.f, 0.f);
    }
}

// ---------------- pipelined FP16 mma.sync grouped GEMM, B converted in smem ----------------
// CTA 128x128, 4 warps (2x2) of 64x64. A: fp16 cp.async 3-stage.
// B: fp32 weights cp.async 3-stage -> per-kt smem convert (LDS.128/cvt/STS.64)
//    into a single fp16 buffer consumed by ldmatrix. No fp16 weight copy in DRAM.
template <int KD, int ND, bool DOGELU>
__global__ void __launch_bounds__(128, 2)
k_hgemm(const float* __restrict__ Bsrc, const float* __restrict__ Bias) {
    extern __shared__ char smem[];

    int row0 = blockIdx.y * BM;
    if (row0 >= g_off[NE]) return;
    int e = 0;
    while (row0 >= g_off[e + 1]) e++;
    int nblk = blockIdx.x * BN;

    const __half* A  = DOGELU ? g_Xh : g_Hh;
    const float* B32 = Bsrc + (size_t)e * KD * ND;

    int tid = threadIdx.x;
    uint32_t sb = smem_u32(smem);
    uint32_t sbB32 = sb + A_TOT;
    uint32_t sbB16 = sb + A_TOT + B32_TOT;

    // A cp.async slots: 128 rows x 4 chunks of 16B (8 halves)
    const __half* aS[4]; uint32_t aD[4];
#pragma unroll
    for (int p = 0; p < 4; p++) {
        int i = tid + 128 * p;
        int r = i >> 2, j = i & 3;
        aS[p] = A + (size_t)(row0 + r) * KD + j * 8;
        aD[p] = sb + r * (APAD * 2) + j * 16;
    }
    // B fp32 cp.async slots + convert slots: 32 k-rows x 32 chunks of 16B (4 floats)
    const float* b32S[8]; uint32_t b32D[8], b16W[8];
#pragma unroll
    for (int p = 0; p < 8; p++) {
        int c = tid + 128 * p;
        int kr = c >> 5, j = c & 31;
        b32S[p] = B32 + (size_t)kr * ND + nblk + j * 4;
        b32D[p] = sbB32 + kr * (B32PAD * 4) + j * 16;
        b16W[p] = sbB16 + kr * (BPAD * 2) + j * 8;
    }

    const int NKT = KD / BK;

    auto LOAD = [&](int kt) {
        uint32_t stA = (kt % STAGES) * ABYTES;
        uint32_t stB = (kt % STAGES) * B32BYTES;
        size_t ka = (size_t)kt * BK;
        size_t kb = (size_t)kt * BK * ND;
#pragma unroll
        for (int p = 0; p < 4; p++) cpa16(aD[p] + stA, aS[p] + ka);
#pragma unroll
        for (int p = 0; p < 8; p++) cpa16(b32D[p] + stB, b32S[p] + kb);
        asm volatile("cp.async.commit_group;" ::: "memory");
    };

    LOAD(0); LOAD(1);

    float acc[4][8][4];
#pragma unroll
    for (int mi = 0; mi < 4; mi++)
#pragma unroll
        for (int ni = 0; ni < 8; ni++)
#pragma unroll
            for (int q = 0; q < 4; q++) acc[mi][ni][q] = 0.f;

    int wid = tid >> 5, lane = tid & 31;
    int g = lane >> 2, tg = lane & 3;
    int wm = (wid >> 1) * 64, wn = (wid & 1) * 64;
    int lane8 = lane & 7, laneb = (lane >> 3) & 1, laneh = lane >> 4;

    uint32_t aAddr0 = sb + ((wm + lane8 + laneb * 8) * APAD + laneh * 8) * 2;
    uint32_t bAddr0 = sbB16 + ((lane8 + laneb * 8) * BPAD + wn + laneh * 8) * 2;

    for (int kt = 0; kt < NKT; kt++) {
        asm volatile("cp.async.wait_group %0;" :: "n"(STAGES - 2));
        __syncthreads();
        if (kt + STAGES - 1 < NKT) LOAD(kt + STAGES - 1);
        else asm volatile("cp.async.commit_group;" ::: "memory");

        // convert B stage kt: fp32 smem -> fp16 smem (single buffer; the
        // barriers on either side order these writes w.r.t. ldmatrix reads)
        {
            uint32_t st32 = (kt % STAGES) * B32BYTES;
#pragma unroll
            for (int p = 0; p < 8; p++) {
                float4 v;
                lds128(v, b32D[p] + st32 - (tid >> 5) * 0);  // b32D already absolute; add stage
            }
        }
        // (the loop above was folded below to keep registers transient)
        {
            uint32_t st32 = (kt % STAGES) * B32BYTES;
#pragma unroll
            for (int p = 0; p < 8; p++) {
                float4 v;
                lds128(v, b32D[p] + st32);
                uint32_t u0 = h2u(__floats2half2_rn(v.x, v.y));
                uint32_t u1 = h2u(__floats2half2_rn(v.z, v.w));
                sts64(b16W[p], u0, u1);
            }
        }
        __syncthreads();

        uint32_t stA = (kt % STAGES) * ABYTES;
#pragma unroll
        for (int ks = 0; ks < BK; ks += 16) {
            unsigned af[4][4], bf[8][2];
#pragma unroll
            for (int mi = 0; mi < 4; mi++)
                ldsm4(af[mi], aAddr0 + stA + (mi * 16 * APAD + ks) * 2);
#pragma unroll
            for (int np = 0; np < 4; np++) {
                unsigned r[4];
                ldsm4t(r, bAddr0 + (ks * BPAD + np * 16) * 2);
                bf[2 * np][0] = r[0]; bf[2 * np][1] = r[1];
                bf[2 * np + 1][0] = r[2]; bf[2 * np + 1][1] = r[3];
            }
#pragma unroll
            for (int mi = 0; mi < 4; mi++)
#pragma unroll
                for (int ni = 0; ni < 8; ni++) {
                    asm volatile(
                        "mma.sync.aligned.m16n8k16.row.col.f32.f16.f16.f32 "
                        "{%0,%1,%2,%3}, {%4,%5,%6,%7}, {%8,%9}, {%0,%1,%2,%3};\n"
                        : "+f"(acc[mi][ni][0]), "+f"(acc[mi][ni][1]),
                          "+f"(acc[mi][ni][2]), "+f"(acc[mi][ni][3])
                        : "r"(af[mi][0]), "r"(af[mi][1]), "r"(af[mi][2]), "r"(af[mi][3]),
                          "r"(bf[ni][0]), "r"(bf[ni][1]));
                }
        }
    }

    asm volatile("cp.async.wait_group 0;" ::: "memory");

    // epilogue
    const float* bias = Bias + (size_t)e * ND + nblk;
    float bv[16];
#pragma unroll
    for (int ni = 0; ni < 8; ni++) {
        bv[2 * ni]     = bias[wn + ni * 8 + 2 * tg];
        bv[2 * ni + 1] = bias[wn + ni * 8 + 2 * tg + 1];
    }
#pragma unroll
    for (int mi = 0; mi < 4; mi++) {
        int rr = row0 + wm + mi * 16 + g;
#pragma unroll
        for (int ni = 0; ni < 8; ni++) {
            float v0 = acc[mi][ni][0] + bv[2 * ni];
            float v1 = acc[mi][ni][1] + bv[2 * ni + 1];
            float v2 = acc[mi][ni][2] + bv[2 * ni];
            float v3 = acc[mi][ni][3] + bv[2 * ni + 1];
            int nc = wn + ni * 8 + 2 * tg;
            if (DOGELU) {
                v0 = 0.5f * v0 * (1.f + erff(v0 * 0.70710678118654752f));
                v1 = 0.5f * v1 * (1.f + erff(v1 * 0.70710678118654752f));
                v2 = 0.5f * v2 * (1.f + erff(v2 * 0.70710678118654752f));
                v3 = 0.5f * v3 * (1.f + erff(v3 * 0.70710678118654752f));
                __half2* h0 = (__half2*)(g_Hh + (size_t)rr * ND + nblk + nc);
                __half2* h1 = (__half2*)(g_Hh + (size_t)(rr + 8) * ND + nblk + nc);
                *h0 = __floats2half2_rn(v0, v1);
                *h1 = __floats2half2_rn(v2, v3);
            } else {
                __half2* y0 = (__half2*)(g_Yh + (size_t)rr * ND + nblk + nc);
                __half2* y1 = (__half2*)(g_Yh + (size_t)(rr + 8) * ND + nblk + nc);
                *y0 = __floats2half2_rn(v0, v1);
                *y1 = __floats2half2_rn(v2, v3);
            }
        }
    }
}

// ---------------- combine: out[t] = w0*Y[pos0] + w1*Y[pos1]  (fp16 Y, fp32 out) ----------------
__global__ void k_combine(float* __restrict__ out) {
    int t = blockIdx.x;
    int p0 = g_pairPos[2 * t], p1 = g_pairPos[2 * t + 1];
    float w0 = g_w2v[2 * t], w1 = g_w2v[2 * t + 1];
    const uint4* y0 = (const uint4*)(g_Yh + (size_t)p0 * HID);
    const uint4* y1 = (const uint4*)(g_Yh + (size_t)p1 * HID);
    float4* o = (float4*)(out + (size_t)t * HID);
    int i = threadIdx.x;                 // 128 threads * 8 halves
    uint4 a = y0[i], b = y1[i];
    const __half2* ah = (const __half2*)&a;
    const __half2* bh = (const __half2*)&b;
    float4 r0, r1;
    float2 a0 = __half22float2(ah[0]), b0 = __half22float2(bh[0]);
    float2 a1 = __half22float2(ah[1]), b1 = __half22float2(bh[1]);
    float2 a2 = __half22float2(ah[2]), b2 = __half22float2(bh[2]);
    float2 a3 = __half22float2(ah[3]), b3 = __half22float2(bh[3]);
    r0.x = w0 * a0.x + w1 * b0.x;  r0.y = w0 * a0.y + w1 * b0.y;
    r0.z = w0 * a1.x + w1 * b1.x;  r0.w = w0 * a1.y + w1 * b1.y;
    r1.x = w0 * a2.x + w1 * b2.x;  r1.y = w0 * a2.y + w1 * b2.y;
    r1.z = w0 * a3.x + w1 * b3.x;  r1.w = w0 * a3.y + w1 * b3.y;
    o[2 * i]     = r0;
    o[2 * i + 1] = r1;
}

// ---------------- launch ----------------
extern "C" void kernel_launch(void* const* d_in, const int* in_sizes, int n_in,
                              void* d_out, int out_size) {
    const float* x  = (const float*)d_in[0];
    const float* Wr = (const float*)d_in[1];
    const float* W1 = (const float*)d_in[2];
    const float* b1 = (const float*)d_in[3];
    const float* W2 = (const float*)d_in[4];
    const float* b2 = (const float*)d_in[5];
    float* out = (float*)d_out;

    cudaFuncSetAttribute((const void*)k_hgemm<HID, FFN, true>,
                         cudaFuncAttributeMaxDynamicSharedMemorySize, SMEM_TOTAL);
    cudaFuncSetAttribute((const void*)k_hgemm<FFN, HID, false>,
                         cudaFuncAttributeMaxDynamicSharedMemorySize, SMEM_TOTAL);

    k_router<<<NTOK / 8, 256>>>(x, Wr);
    k_offsets<<<1, 32>>>();
    k_place<<<(NTOK * 2) / 256, 256>>>();
    k_gather<<<CAP, 256>>>(x);

    k_hgemm<HID, FFN, true><<<dim3(FFN / BN, CAP / BM), 128, SMEM_TOTAL>>>(W1, b1);
    k_hgemm<FFN, HID, false><<<dim3(HID / BN, CAP / BM), 128, SMEM_TOTAL>>>(W2, b2);
    k_combine<<<NTOK, 128>>>(out);
}

// round 11
// speedup vs baseline: 1.3790x; 1.3790x over previous
#include <cuda_runtime.h>
#include <cuda_fp16.h>
#include <math.h>
#include <stdint.h>

#define HID  1024
#define FFN  4096
#define NE   8
#define NTOK 4096
#define CAP  9216

#define BM 128
#define BN 128
#define BK 32
#define STAGES 4
#define APAD 40                        // halves per A smem row (80 B, conflict-free LDSM)
#define BPAD 136                       // halves per B smem k-row (272 B, conflict-free LDSM)
#define ABYTES (BM * APAD * 2)         // 10240
#define BBYTES (BK * BPAD * 2)         // 8704
#define STGB   (ABYTES + BBYTES)       // 18944
#define SMEM_TOTAL (STAGES * STGB)     // 75776 -> 2 CTAs/SM

// ---------------- scratch (device globals; zero-initialized at load) ----------------
__device__ int    g_cnt[NE];
__device__ int    g_off[NE + 1];
__device__ int    g_end[NE];
__device__ int    g_cur[NE];
__device__ int    g_rowTok[CAP];
__device__ float  g_rowW[CAP];
__device__ int    g_tok2[NTOK * 2];
__device__ float  g_w2v[NTOK * 2];
__device__ __half g_Xh[(size_t)CAP * HID];
__device__ __half g_Hh[(size_t)CAP * FFN];
__device__ __half g_W1h[(size_t)NE * HID * FFN];
__device__ __half g_W2h[(size_t)NE * FFN * HID];

// ---------------- helpers ----------------
__device__ __forceinline__ uint32_t smem_u32(const void* p) {
    uint32_t a;
    asm("{ .reg .u64 t; cvta.to.shared.u64 t, %1; cvt.u32.u64 %0, t; }" : "=r"(a) : "l"(p));
    return a;
}
__device__ __forceinline__ void cpa16(uint32_t s, const void* g) {
    asm volatile("cp.async.cg.shared.global [%0], [%1], 16;\n" :: "r"(s), "l"(g));
}
__device__ __forceinline__ void ldsm4(unsigned* r, uint32_t a) {
    asm volatile("ldmatrix.sync.aligned.m8n8.x4.shared.b16 {%0,%1,%2,%3}, [%4];"
                 : "=r"(r[0]), "=r"(r[1]), "=r"(r[2]), "=r"(r[3]) : "r"(a));
}
__device__ __forceinline__ void ldsm4t(unsigned* r, uint32_t a) {
    asm volatile("ldmatrix.sync.aligned.m8n8.x4.trans.shared.b16 {%0,%1,%2,%3}, [%4];"
                 : "=r"(r[0]), "=r"(r[1]), "=r"(r[2]), "=r"(r[3]) : "r"(a));
}

// ---------------- fused prep: zero counters + zero output + convert weights ----------------
__global__ void k_prep(const float* __restrict__ W1, const float* __restrict__ W2,
                       float* __restrict__ out) {
    if (blockIdx.x == 0 && threadIdx.x < NE) g_cnt[threadIdx.x] = 0;
    int tid0 = blockIdx.x * blockDim.x + threadIdx.x;
    int stride = gridDim.x * blockDim.x;
    // zero the output accumulator (harness poisons it)
    {
        float4* o = (float4*)out;
        const int no4 = NTOK * HID / 4;
        for (int i = tid0; i < no4; i += stride)
            o[i] = make_float4(0.f, 0.f, 0.f, 0.f);
    }
    const int n4 = NE * HID * FFN / 4;   // same element count for both slabs
    __half2* d1 = (__half2*)g_W1h;
    __half2* d2 = (__half2*)g_W2h;
    const float4* s1 = (const float4*)W1;
    const float4* s2 = (const float4*)W2;
    for (int i = tid0; i < n4; i += stride) {
        float4 v = s1[i];
        d1[2 * i]     = __floats2half2_rn(v.x, v.y);
        d1[2 * i + 1] = __floats2half2_rn(v.z, v.w);
        float4 u = s2[i];
        d2[2 * i]     = __floats2half2_rn(u.x, u.y);
        d2[2 * i + 1] = __floats2half2_rn(u.z, u.w);
    }
}

// ---------------- routing ----------------
__global__ void k_router(const float* __restrict__ x, const float* __restrict__ Wr) {
    int warp = threadIdx.x >> 5, lane = threadIdx.x & 31;
    int t = blockIdx.x * 8 + warp;
    const float* xr = x + (size_t)t * HID;
    float acc[NE];
#pragma unroll
    for (int e = 0; e < NE; e++) acc[e] = 0.f;
    for (int i = lane; i < HID; i += 32) {
        float xv = xr[i];
        const float4* w = (const float4*)(Wr + (size_t)i * NE);
        float4 w0 = w[0], w1 = w[1];
        acc[0] += xv * w0.x; acc[1] += xv * w0.y; acc[2] += xv * w0.z; acc[3] += xv * w0.w;
        acc[4] += xv * w1.x; acc[5] += xv * w1.y; acc[6] += xv * w1.z; acc[7] += xv * w1.w;
    }
#pragma unroll
    for (int e = 0; e < NE; e++)
#pragma unroll
        for (int s = 16; s > 0; s >>= 1) acc[e] += __shfl_xor_sync(0xffffffffu, acc[e], s);
    if (lane == 0) {
        int i0 = 0; float m0 = acc[0];
#pragma unroll
        for (int e = 1; e < NE; e++) if (acc[e] > m0) { m0 = acc[e]; i0 = e; }
        int i1 = -1; float m1 = -1e30f;
#pragma unroll
        for (int e = 0; e < NE; e++) if (e != i0 && acc[e] > m1) { m1 = acc[e]; i1 = e; }
        float w0 = 1.f / (1.f + expf(m1 - m0));
        g_tok2[2 * t] = i0; g_tok2[2 * t + 1] = i1;
        g_w2v[2 * t] = w0;  g_w2v[2 * t + 1] = 1.f - w0;
        atomicAdd(&g_cnt[i0], 1);
        atomicAdd(&g_cnt[i1], 1);
    }
}

__global__ void k_offsets() {
    if (threadIdx.x == 0) {
        int o = 0;
#pragma unroll
        for (int e = 0; e < NE; e++) {
            int c = g_cnt[e];
            g_off[e] = o; g_end[e] = o + c; g_cur[e] = o;
            o += (c + 127) & ~127;
        }
        g_off[NE] = o;
    }
}

__global__ void k_place() {
    int p = blockIdx.x * blockDim.x + threadIdx.x;
    if (p < NTOK * 2) {
        int e = g_tok2[p];
        int r = atomicAdd(&g_cur[e], 1);
        g_rowTok[r] = p >> 1;
        g_rowW[r]   = g_w2v[p];
    }
}

// gather + fp16-convert x into g_Xh; zero pad rows
__global__ void k_gather(const float* __restrict__ x) {
    int r = blockIdx.x;
    bool valid = false;
#pragma unroll
    for (int e = 0; e < NE; e++) valid |= (r >= g_off[e] && r < g_end[e]);
    __half2* dst = (__half2*)(g_Xh + (size_t)r * HID);
    int i = threadIdx.x;  // 256 threads * 4 floats
    if (valid) {
        const float4* src = (const float4*)(x + (size_t)g_rowTok[r] * HID);
        float4 v = src[i];
        dst[2 * i]     = __floats2half2_rn(v.x, v.y);
        dst[2 * i + 1] = __floats2half2_rn(v.z, v.w);
    } else {
        dst[2 * i]     = __floats2half2_rn(0.f, 0.f);
        dst[2 * i + 1] = __floats2half2_rn(0.f, 0.f);
    }
}

// ---------------- pipelined FP16 mma.sync grouped GEMM ----------------
// CTA 128x128, 4 warps (2x2) of 64x64, BK=32, 4-stage cp.async, 2 CTAs/SM.
// DOGELU (GEMM1): bias + exact GELU -> g_Hh (fp16).
// !DOGELU (GEMM2): bias, scale by routing weight, atomicAdd into out
//   (each output element gets exactly 2 fp32 adds onto zero -> commutative,
//    so results are bitwise deterministic regardless of CTA order).
template <int KD, int ND, bool DOGELU>
__global__ void __launch_bounds__(128, 2)
k_hgemm(const float* __restrict__ Bias, float* __restrict__ Out) {
    extern __shared__ char smem[];

    int row0 = blockIdx.y * BM;
    if (row0 >= g_off[NE]) return;
    int e = 0;
    while (row0 >= g_off[e + 1]) e++;
    int rend = g_end[e];
    int nblk = blockIdx.x * BN;

    const __half* A = DOGELU ? g_Xh : g_Hh;
    const __half* B = (DOGELU ? g_W1h : g_W2h) + (size_t)e * KD * ND;

    int tid = threadIdx.x;
    uint32_t sb = smem_u32(smem);

    // cp.async slots: A = 128 rows x 4 chunks(16B=8 halves); B = 32 k-rows x 16 chunks
    const __half* aS[4]; uint32_t aD[4];
    const __half* bS[4]; uint32_t bD[4];
#pragma unroll
    for (int p = 0; p < 4; p++) {
        int i = tid + 128 * p;
        int r = i >> 2, j = i & 3;
        aS[p] = A + (size_t)(row0 + r) * KD + j * 8;
        aD[p] = sb + r * (APAD * 2) + j * 16;
    }
#pragma unroll
    for (int p = 0; p < 4; p++) {
        int i = tid + 128 * p;
        int kr = i >> 4, j = i & 15;
        bS[p] = B + (size_t)kr * ND + nblk + j * 8;
        bD[p] = sb + ABYTES + kr * (BPAD * 2) + j * 16;
    }

    const int NKT = KD / BK;

    auto LOAD = [&](int kt) {
        uint32_t st = (kt % STAGES) * STGB;
        size_t ka = (size_t)kt * BK;
        size_t kb = (size_t)kt * BK * ND;
#pragma unroll
        for (int p = 0; p < 4; p++) cpa16(aD[p] + st, aS[p] + ka);
#pragma unroll
        for (int p = 0; p < 4; p++) cpa16(bD[p] + st, bS[p] + kb);
        asm volatile("cp.async.commit_group;" ::: "memory");
    };

    LOAD(0); LOAD(1); LOAD(2);

    float acc[4][8][4];
#pragma unroll
    for (int mi = 0; mi < 4; mi++)
#pragma unroll
        for (int ni = 0; ni < 8; ni++)
#pragma unroll
            for (int q = 0; q < 4; q++) acc[mi][ni][q] = 0.f;

    int wid = tid >> 5, lane = tid & 31;
    int g = lane >> 2, tg = lane & 3;
    int wm = (wid >> 1) * 64, wn = (wid & 1) * 64;
    int lane8 = lane & 7, laneb = (lane >> 3) & 1, laneh = lane >> 4;

    uint32_t aAddr0 = sb + ((wm + lane8 + laneb * 8) * APAD + laneh * 8) * 2;
    uint32_t bAddr0 = sb + ABYTES + ((lane8 + laneb * 8) * BPAD + wn + laneh * 8) * 2;

    for (int kt = 0; kt < NKT; kt++) {
        asm volatile("cp.async.wait_group %0;" :: "n"(STAGES - 2));
        __syncthreads();
        if (kt + STAGES - 1 < NKT) LOAD(kt + STAGES - 1);
        else asm volatile("cp.async.commit_group;" ::: "memory");

        uint32_t st = (kt % STAGES) * STGB;
#pragma unroll
        for (int ks = 0; ks < BK; ks += 16) {
            unsigned af[4][4], bf[8][2];
#pragma unroll
            for (int mi = 0; mi < 4; mi++)
                ldsm4(af[mi], aAddr0 + st + (mi * 16 * APAD + ks) * 2);
#pragma unroll
            for (int np = 0; np < 4; np++) {
                unsigned r[4];
                ldsm4t(r, bAddr0 + st + (ks * BPAD + np * 16) * 2);
                bf[2 * np][0] = r[0]; bf[2 * np][1] = r[1];
                bf[2 * np + 1][0] = r[2]; bf[2 * np + 1][1] = r[3];
            }
#pragma unroll
            for (int mi = 0; mi < 4; mi++)
#pragma unroll
                for (int ni = 0; ni < 8; ni++) {
                    asm volatile(
                        "mma.sync.aligned.m16n8k16.row.col.f32.f16.f16.f32 "
                        "{%0,%1,%2,%3}, {%4,%5,%6,%7}, {%8,%9}, {%0,%1,%2,%3};\n"
                        : "+f"(acc[mi][ni][0]), "+f"(acc[mi][ni][1]),
                          "+f"(acc[mi][ni][2]), "+f"(acc[mi][ni][3])
                        : "r"(af[mi][0]), "r"(af[mi][1]), "r"(af[mi][2]), "r"(af[mi][3]),
                          "r"(bf[ni][0]), "r"(bf[ni][1]));
                }
        }
    }

    asm volatile("cp.async.wait_group 0;" ::: "memory");

    // epilogue
    const float* bias = Bias + (size_t)e * ND + nblk;
    float bv[16];
#pragma unroll
    for (int ni = 0; ni < 8; ni++) {
        bv[2 * ni]     = bias[wn + ni * 8 + 2 * tg];
        bv[2 * ni + 1] = bias[wn + ni * 8 + 2 * tg + 1];
    }
#pragma unroll
    for (int mi = 0; mi < 4; mi++) {
        int rr = row0 + wm + mi * 16 + g;
        if (DOGELU) {
#pragma unroll
            for (int ni = 0; ni < 8; ni++) {
                float v0 = acc[mi][ni][0] + bv[2 * ni];
                float v1 = acc[mi][ni][1] + bv[2 * ni + 1];
                float v2 = acc[mi][ni][2] + bv[2 * ni];
                float v3 = acc[mi][ni][3] + bv[2 * ni + 1];
                v0 = 0.5f * v0 * (1.f + erff(v0 * 0.70710678118654752f));
                v1 = 0.5f * v1 * (1.f + erff(v1 * 0.70710678118654752f));
                v2 = 0.5f * v2 * (1.f + erff(v2 * 0.70710678118654752f));
                v3 = 0.5f * v3 * (1.f + erff(v3 * 0.70710678118654752f));
                int nc = wn + ni * 8 + 2 * tg;
                __half2* h0 = (__half2*)(g_Hh + (size_t)rr * ND + nblk + nc);
                __half2* h1 = (__half2*)(g_Hh + (size_t)(rr + 8) * ND + nblk + nc);
                *h0 = __floats2half2_rn(v0, v1);
                *h1 = __floats2half2_rn(v2, v3);
            }
        } else {
            bool ok0 = rr < rend, ok1 = (rr + 8) < rend;
            int   tk0 = ok0 ? g_rowTok[rr] : 0;
            int   tk1 = ok1 ? g_rowTok[rr + 8] : 0;
            float w0r = ok0 ? g_rowW[rr] : 0.f;
            float w1r = ok1 ? g_rowW[rr + 8] : 0.f;
            float* o0 = Out + (size_t)tk0 * ND + nblk;
            float* o1 = Out + (size_t)tk1 * ND + nblk;
#pragma unroll
            for (int ni = 0; ni < 8; ni++) {
                int nc = wn + ni * 8 + 2 * tg;
                if (ok0) {
                    atomicAdd(o0 + nc,     w0r * (acc[mi][ni][0] + bv[2 * ni]));
                    atomicAdd(o0 + nc + 1, w0r * (acc[mi][ni][1] + bv[2 * ni + 1]));
                }
                if (ok1) {
                    atomicAdd(o1 + nc,     w1r * (acc[mi][ni][2] + bv[2 * ni]));
                    atomicAdd(o1 + nc + 1, w1r * (acc[mi][ni][3] + bv[2 * ni + 1]));
                }
            }
        }
    }
}

// ---------------- launch ----------------
extern "C" void kernel_launch(void* const* d_in, const int* in_sizes, int n_in,
                              void* d_out, int out_size) {
    const float* x  = (const float*)d_in[0];
    const float* Wr = (const float*)d_in[1];
    const float* W1 = (const float*)d_in[2];
    const float* b1 = (const float*)d_in[3];
    const float* W2 = (const float*)d_in[4];
    const float* b2 = (const float*)d_in[5];
    float* out = (float*)d_out;

    cudaFuncSetAttribute((const void*)k_hgemm<HID, FFN, true>,
                         cudaFuncAttributeMaxDynamicSharedMemorySize, SMEM_TOTAL);
    cudaFuncSetAttribute((const void*)k_hgemm<FFN, HID, false>,
                         cudaFuncAttributeMaxDynamicSharedMemorySize, SMEM_TOTAL);

    k_prep<<<2048, 256>>>(W1, W2, out);
    k_router<<<NTOK / 8, 256>>>(x, Wr);
    k_offsets<<<1, 32>>>();
    k_place<<<(NTOK * 2) / 256, 256>>>();
    k_gather<<<CAP, 256>>>(x);

    k_hgemm<HID, FFN, true><<<dim3(FFN / BN, CAP / BM), 128, SMEM_TOTAL>>>(b1, nullptr);
    k_hgemm<FFN, HID, false><<<dim3(HID / BN, CAP / BM), 128, SMEM_TOTAL>>>(b2, out);
}

// round 12
// speedup vs baseline: 1.3951x; 1.0117x over previous
#include <cuda_runtime.h>
#include <cuda_fp16.h>
#include <math.h>
#include <stdint.h>

#define HID  1024
#define FFN  4096
#define NE   8
#define NTOK 4096
#define ECAP 1536                      // fixed rows per expert segment (18-sigma safe)
#define CAPR (NE * ECAP)               // 12288 total rows

#define BM 128
#define BN 128
#define BK 32
#define STAGES 4
#define APAD 40                        // halves per A smem row (80 B, conflict-free LDSM)
#define BPAD 136                       // halves per B smem k-row (272 B, conflict-free LDSM)
#define ABYTES (BM * APAD * 2)         // 10240
#define BBYTES (BK * BPAD * 2)         // 8704
#define STGB   (ABYTES + BBYTES)       // 18944
#define SMEM_TOTAL (STAGES * STGB)     // 75776 -> 2 CTAs/SM

// ---------------- scratch (device globals; zero-initialized at load) ----------------
__device__ int    g_cnt[NE];
__device__ int    g_rowTok[CAPR];
__device__ float  g_rowW[CAPR];
__device__ __half g_Xh[(size_t)CAPR * HID];
__device__ __half g_Hh[(size_t)CAPR * FFN];
__device__ __half g_W1h[(size_t)NE * HID * FFN];
__device__ __half g_W2h[(size_t)NE * FFN * HID];

// ---------------- helpers ----------------
__device__ __forceinline__ uint32_t smem_u32(const void* p) {
    uint32_t a;
    asm("{ .reg .u64 t; cvta.to.shared.u64 t, %1; cvt.u32.u64 %0, t; }" : "=r"(a) : "l"(p));
    return a;
}
__device__ __forceinline__ void cpa16(uint32_t s, const void* g) {
    asm volatile("cp.async.cg.shared.global [%0], [%1], 16;\n" :: "r"(s), "l"(g));
}
__device__ __forceinline__ void ldsm4(unsigned* r, uint32_t a) {
    asm volatile("ldmatrix.sync.aligned.m8n8.x4.shared.b16 {%0,%1,%2,%3}, [%4];"
                 : "=r"(r[0]), "=r"(r[1]), "=r"(r[2]), "=r"(r[3]) : "r"(a));
}
__device__ __forceinline__ void ldsm4t(unsigned* r, uint32_t a) {
    asm volatile("ldmatrix.sync.aligned.m8n8.x4.trans.shared.b16 {%0,%1,%2,%3}, [%4];"
                 : "=r"(r[0]), "=r"(r[1]), "=r"(r[2]), "=r"(r[3]) : "r"(a));
}

// ---------------- fused prep: zero counters + zero output + convert weights ----------------
__global__ void k_prep(const float* __restrict__ W1, const float* __restrict__ W2,
                       float* __restrict__ out) {
    if (blockIdx.x == 0 && threadIdx.x < NE) g_cnt[threadIdx.x] = 0;
    int tid0 = blockIdx.x * blockDim.x + threadIdx.x;
    int stride = gridDim.x * blockDim.x;
    {
        float4* o = (float4*)out;
        const int no4 = NTOK * HID / 4;
        for (int i = tid0; i < no4; i += stride)
            o[i] = make_float4(0.f, 0.f, 0.f, 0.f);
    }
    const int n4 = NE * HID * FFN / 4;
    __half2* d1 = (__half2*)g_W1h;
    __half2* d2 = (__half2*)g_W2h;
    const float4* s1 = (const float4*)W1;
    const float4* s2 = (const float4*)W2;
    for (int i = tid0; i < n4; i += stride) {
        float4 v = s1[i];
        d1[2 * i]     = __floats2half2_rn(v.x, v.y);
        d1[2 * i + 1] = __floats2half2_rn(v.z, v.w);
        float4 u = s2[i];
        d2[2 * i]     = __floats2half2_rn(u.x, u.y);
        d2[2 * i + 1] = __floats2half2_rn(u.z, u.w);
    }
}

// ---------------- router: top-2 + pairwise softmax + direct fixed-segment placement ----------------
__global__ void k_router(const float* __restrict__ x, const float* __restrict__ Wr) {
    int warp = threadIdx.x >> 5, lane = threadIdx.x & 31;
    int t = blockIdx.x * 8 + warp;
    const float* xr = x + (size_t)t * HID;
    float acc[NE];
#pragma unroll
    for (int e = 0; e < NE; e++) acc[e] = 0.f;
    for (int i = lane; i < HID; i += 32) {
        float xv = xr[i];
        const float4* w = (const float4*)(Wr + (size_t)i * NE);
        float4 w0 = w[0], w1 = w[1];
        acc[0] += xv * w0.x; acc[1] += xv * w0.y; acc[2] += xv * w0.z; acc[3] += xv * w0.w;
        acc[4] += xv * w1.x; acc[5] += xv * w1.y; acc[6] += xv * w1.z; acc[7] += xv * w1.w;
    }
#pragma unroll
    for (int e = 0; e < NE; e++)
#pragma unroll
        for (int s = 16; s > 0; s >>= 1) acc[e] += __shfl_xor_sync(0xffffffffu, acc[e], s);
    if (lane == 0) {
        int i0 = 0; float m0 = acc[0];
#pragma unroll
        for (int e = 1; e < NE; e++) if (acc[e] > m0) { m0 = acc[e]; i0 = e; }
        int i1 = -1; float m1 = -1e30f;
#pragma unroll
        for (int e = 0; e < NE; e++) if (e != i0 && acc[e] > m1) { m1 = acc[e]; i1 = e; }
        float w0 = 1.f / (1.f + expf(m1 - m0));
        int r0 = i0 * ECAP + atomicAdd(&g_cnt[i0], 1);
        g_rowTok[r0] = t; g_rowW[r0] = w0;
        int r1 = i1 * ECAP + atomicAdd(&g_cnt[i1], 1);
        g_rowTok[r1] = t; g_rowW[r1] = 1.f - w0;
    }
}

// gather + fp16-convert x into g_Xh; zero pad rows up to the 128 boundary
__global__ void k_gather(const float* __restrict__ x) {
    int r = blockIdx.x;
    int e = r / ECAP;
    int rl = r - e * ECAP;
    int c = g_cnt[e];
    __half2* dst = (__half2*)(g_Xh + (size_t)r * HID);
    int i = threadIdx.x;  // 256 threads * 4 floats
    if (rl < c) {
        const float4* src = (const float4*)(x + (size_t)g_rowTok[r] * HID);
        float4 v = src[i];
        dst[2 * i]     = __floats2half2_rn(v.x, v.y);
        dst[2 * i + 1] = __floats2half2_rn(v.z, v.w);
    } else if (rl < ((c + 127) & ~127)) {
        dst[2 * i]     = __floats2half2_rn(0.f, 0.f);
        dst[2 * i + 1] = __floats2half2_rn(0.f, 0.f);
    }
}

// ---------------- pipelined FP16 mma.sync grouped GEMM ----------------
// CTA 128x128, 4 warps (2x2) of 64x64, BK=32, 4-stage cp.async, 2 CTAs/SM.
// DOGELU (GEMM1): bias + exact GELU -> g_Hh (fp16).
// !DOGELU (GEMM2): bias, scale by routing weight, atomicAdd into out
//   (each output element gets exactly 2 fp32 adds onto zero -> commutative,
//    so results are bitwise deterministic regardless of CTA order).
template <int KD, int ND, bool DOGELU>
__global__ void __launch_bounds__(128, 2)
k_hgemm(const float* __restrict__ Bias, float* __restrict__ Out) {
    extern __shared__ char smem[];

    int row0 = blockIdx.y * BM;
    int e = row0 / ECAP;
    int rl0 = row0 - e * ECAP;
    int cnt = g_cnt[e];
    if (rl0 >= cnt) return;
    int rend = e * ECAP + cnt;
    int nblk = blockIdx.x * BN;

    const __half* A = DOGELU ? g_Xh : g_Hh;
    const __half* B = (DOGELU ? g_W1h : g_W2h) + (size_t)e * KD * ND;

    int tid = threadIdx.x;
    uint32_t sb = smem_u32(smem);

    // cp.async slots: A = 128 rows x 4 chunks(16B=8 halves); B = 32 k-rows x 16 chunks
    const __half* aS[4]; uint32_t aD[4];
    const __half* bS[4]; uint32_t bD[4];
#pragma unroll
    for (int p = 0; p < 4; p++) {
        int i = tid + 128 * p;
        int r = i >> 2, j = i & 3;
        aS[p] = A + (size_t)(row0 + r) * KD + j * 8;
        aD[p] = sb + r * (APAD * 2) + j * 16;
    }
#pragma unroll
    for (int p = 0; p < 4; p++) {
        int i = tid + 128 * p;
        int kr = i >> 4, j = i & 15;
        bS[p] = B + (size_t)kr * ND + nblk + j * 8;
        bD[p] = sb + ABYTES + kr * (BPAD * 2) + j * 16;
    }

    const int NKT = KD / BK;

    auto LOAD = [&](int kt) {
        uint32_t st = (kt % STAGES) * STGB;
        size_t ka = (size_t)kt * BK;
        size_t kb = (size_t)kt * BK * ND;
#pragma unroll
        for (int p = 0; p < 4; p++) cpa16(aD[p] + st, aS[p] + ka);
#pragma unroll
        for (int p = 0; p < 4; p++) cpa16(bD[p] + st, bS[p] + kb);
        asm volatile("cp.async.commit_group;" ::: "memory");
    };

    LOAD(0); LOAD(1); LOAD(2);

    float acc[4][8][4];
#pragma unroll
    for (int mi = 0; mi < 4; mi++)
#pragma unroll
        for (int ni = 0; ni < 8; ni++)
#pragma unroll
            for (int q = 0; q < 4; q++) acc[mi][ni][q] = 0.f;

    int wid = tid >> 5, lane = tid & 31;
    int g = lane >> 2, tg = lane & 3;
    int wm = (wid >> 1) * 64, wn = (wid & 1) * 64;
    int lane8 = lane & 7, laneb = (lane >> 3) & 1, laneh = lane >> 4;

    uint32_t aAddr0 = sb + ((wm + lane8 + laneb * 8) * APAD + laneh * 8) * 2;
    uint32_t bAddr0 = sb + ABYTES + ((lane8 + laneb * 8) * BPAD + wn + laneh * 8) * 2;

    for (int kt = 0; kt < NKT; kt++) {
        asm volatile("cp.async.wait_group %0;" :: "n"(STAGES - 2));
        __syncthreads();
        if (kt + STAGES - 1 < NKT) LOAD(kt + STAGES - 1);
        else asm volatile("cp.async.commit_group;" ::: "memory");

        uint32_t st = (kt % STAGES) * STGB;
#pragma unroll
        for (int ks = 0; ks < BK; ks += 16) {
            unsigned af[4][4], bf[8][2];
#pragma unroll
            for (int mi = 0; mi < 4; mi++)
                ldsm4(af[mi], aAddr0 + st + (mi * 16 * APAD + ks) * 2);
#pragma unroll
            for (int np = 0; np < 4; np++) {
                unsigned r[4];
                ldsm4t(r, bAddr0 + st + (ks * BPAD + np * 16) * 2);
                bf[2 * np][0] = r[0]; bf[2 * np][1] = r[1];
                bf[2 * np + 1][0] = r[2]; bf[2 * np + 1][1] = r[3];
            }
#pragma unroll
            for (int mi = 0; mi < 4; mi++)
#pragma unroll
                for (int ni = 0; ni < 8; ni++) {
                    asm volatile(
                        "mma.sync.aligned.m16n8k16.row.col.f32.f16.f16.f32 "
                        "{%0,%1,%2,%3}, {%4,%5,%6,%7}, {%8,%9}, {%0,%1,%2,%3};\n"
                        : "+f"(acc[mi][ni][0]), "+f"(acc[mi][ni][1]),
                          "+f"(acc[mi][ni][2]), "+f"(acc[mi][ni][3])
                        : "r"(af[mi][0]), "r"(af[mi][1]), "r"(af[mi][2]), "r"(af[mi][3]),
                          "r"(bf[ni][0]), "r"(bf[ni][1]));
                }
        }
    }

    asm volatile("cp.async.wait_group 0;" ::: "memory");

    // epilogue
    const float* bias = Bias + (size_t)e * ND + nblk;
    float bv[16];
#pragma unroll
    for (int ni = 0; ni < 8; ni++) {
        bv[2 * ni]     = bias[wn + ni * 8 + 2 * tg];
        bv[2 * ni + 1] = bias[wn + ni * 8 + 2 * tg + 1];
    }
#pragma unroll
    for (int mi = 0; mi < 4; mi++) {
        int rr = row0 + wm + mi * 16 + g;
        if (DOGELU) {
#pragma unroll
            for (int ni = 0; ni < 8; ni++) {
                float v0 = acc[mi][ni][0] + bv[2 * ni];
                float v1 = acc[mi][ni][1] + bv[2 * ni + 1];
                float v2 = acc[mi][ni][2] + bv[2 * ni];
                float v3 = acc[mi][ni][3] + bv[2 * ni + 1];
                v0 = 0.5f * v0 * (1.f + erff(v0 * 0.70710678118654752f));
                v1 = 0.5f * v1 * (1.f + erff(v1 * 0.70710678118654752f));
                v2 = 0.5f * v2 * (1.f + erff(v2 * 0.70710678118654752f));
                v3 = 0.5f * v3 * (1.f + erff(v3 * 0.70710678118654752f));
                int nc = wn + ni * 8 + 2 * tg;
                __half2* h0 = (__half2*)(g_Hh + (size_t)rr * ND + nblk + nc);
                __half2* h1 = (__half2*)(g_Hh + (size_t)(rr + 8) * ND + nblk + nc);
                *h0 = __floats2half2_rn(v0, v1);
                *h1 = __floats2half2_rn(v2, v3);
            }
        } else {
            bool ok0 = rr < rend, ok1 = (rr + 8) < rend;
            int   tk0 = ok0 ? g_rowTok[rr] : 0;
            int   tk1 = ok1 ? g_rowTok[rr + 8] : 0;
            float w0r = ok0 ? g_rowW[rr] : 0.f;
            float w1r = ok1 ? g_rowW[rr + 8] : 0.f;
            float* o0 = Out + (size_t)tk0 * ND + nblk;
            float* o1 = Out + (size_t)tk1 * ND + nblk;
#pragma unroll
            for (int ni = 0; ni < 8; ni++) {
                int nc = wn + ni * 8 + 2 * tg;
                if (ok0) {
                    atomicAdd(o0 + nc,     w0r * (acc[mi][ni][0] + bv[2 * ni]));
                    atomicAdd(o0 + nc + 1, w0r * (acc[mi][ni][1] + bv[2 * ni + 1]));
                }
                if (ok1) {
                    atomicAdd(o1 + nc,     w1r * (acc[mi][ni][2] + bv[2 * ni]));
                    atomicAdd(o1 + nc + 1, w1r * (acc[mi][ni][3] + bv[2 * ni + 1]));
                }
            }
        }
    }
}

// ---------------- launch ----------------
extern "C" void kernel_launch(void* const* d_in, const int* in_sizes, int n_in,
                              void* d_out, int out_size) {
    const float* x  = (const float*)d_in[0];
    const float* Wr = (const float*)d_in[1];
    const float* W1 = (const float*)d_in[2];
    const float* b1 = (const float*)d_in[3];
    const float* W2 = (const float*)d_in[4];
    const float* b2 = (const float*)d_in[5];
    float* out = (float*)d_out;

    cudaFuncSetAttribute((const void*)k_hgemm<HID, FFN, true>,
                         cudaFuncAttributeMaxDynamicSharedMemorySize, SMEM_TOTAL);
    cudaFuncSetAttribute((const void*)k_hgemm<FFN, HID, false>,
                         cudaFuncAttributeMaxDynamicSharedMemorySize, SMEM_TOTAL);

    k_prep<<<2048, 256>>>(W1, W2, out);
    k_router<<<NTOK / 8, 256>>>(x, Wr);
    k_gather<<<CAPR, 256>>>(x);

    k_hgemm<HID, FFN, true><<<dim3(FFN / BN, CAPR / BM), 128, SMEM_TOTAL>>>(b1, nullptr);
    k_hgemm<FFN, HID, false><<<dim3(HID / BN, CAPR / BM), 128, SMEM_TOTAL>>>(b2, out);
}